// round 5
// baseline (speedup 1.0000x reference)
#include <cuda_runtime.h>

#define NB  64
#define CCH 3
#define HH  256
#define WW  256
#define DD  512

struct BParam { float m00, m01, m02, m10, m11, m12, w1, lev; int l0; };

__device__ BParam g_bp[NB];
// HWC4 (channels interleaved, 4th lane zero) image + pyramid.
__device__ float4 g_img4[NB * 256 * 256];
__device__ float4 g_pyr14[NB * 128 * 128];
__device__ float4 g_pyr24[NB * 64 * 64];
__device__ float4 g_pyr34[NB * 32 * 32];

// ---------------------------------------------------------------------------
// Kernel 1: linear head + affine params. One block per batch, 4 warps.
// ---------------------------------------------------------------------------
__global__ void params_kernel(const float* __restrict__ feat,
                              const float* __restrict__ lw,
                              const float* __restrict__ lb,
                              float* __restrict__ out_mat,
                              float* __restrict__ out_aff) {
    int n = blockIdx.x;
    int warp = threadIdx.x >> 5, lane = threadIdx.x & 31;
    const float* f  = feat + n * DD;
    const float* wr = lw + warp * DD;
    float s = 0.f;
    #pragma unroll 4
    for (int k = lane; k < DD; k += 32) s += f[k] * wr[k];
    #pragma unroll
    for (int o = 16; o; o >>= 1) s += __shfl_xor_sync(0xffffffffu, s, o);
    __shared__ float p[4];
    if (lane == 0) p[warp] = s + lb[warp];
    __syncthreads();
    if (threadIdx.x == 0) {
        float rot = tanhf(p[0]) * 3.14159265358979323846f;
        float sc  = expf(p[1]);
        float sx  = p[2], sy = p[3];
        float cs = cosf(rot), sn = sinf(rot);
        float m00 = sc * cs, m01 = -sc * sn, m10 = sc * sn, m11 = sc * cs;
        float* mo = out_mat + n * 6;
        mo[0] = m00; mo[1] = m01; mo[2] = sx;
        mo[3] = m10; mo[4] = m11; mo[5] = sy;
        float* ao = out_aff + n * 4;
        ao[0] = rot; ao[1] = sc; ao[2] = sx; ao[3] = sy;
        // Affine warp: jacobian constant per batch; H==W -> both column norms
        // equal exactly sc. levels = clip(log2(max(sc,1)), 0, 2.5)
        float level = log2f(fmaxf(sc, 1.f));
        level = fminf(fmaxf(level, 0.f), 2.5f);
        int l0 = (int)level;
        if (l0 > 2) l0 = 2;
        BParam bp;
        bp.m00 = m00; bp.m01 = m01; bp.m02 = sx;
        bp.m10 = m10; bp.m11 = m11; bp.m12 = sy;
        bp.w1 = level - (float)l0; bp.l0 = l0; bp.lev = level;
        g_bp[n] = bp;
    }
}

// ---------------------------------------------------------------------------
// Kernel 2: CHW -> HWC4 transpose of img. 4 pixels/thread, float4 both sides.
// ---------------------------------------------------------------------------
__global__ void hwc_kernel(const float* __restrict__ img) {
    int t = blockIdx.x * blockDim.x + threadIdx.x;     // over NB*65536/4
    int idx = t * 4;                                   // n*65536 + h*256 + w
    int n = idx >> 16;
    int hw = idx & 65535;
    const float* p = img + (size_t)n * 3 * 65536 + hw;
    float4 r = *reinterpret_cast<const float4*>(p);
    float4 g = *reinterpret_cast<const float4*>(p + 65536);
    float4 b = *reinterpret_cast<const float4*>(p + 131072);
    g_img4[idx]     = make_float4(r.x, g.x, b.x, 0.f);
    g_img4[idx + 1] = make_float4(r.y, g.y, b.y, 0.f);
    g_img4[idx + 2] = make_float4(r.z, g.z, b.z, 0.f);
    g_img4[idx + 3] = make_float4(r.w, g.w, b.w, 0.f);
}

// ---------------------------------------------------------------------------
// Downsample pair helper: 2 horizontally adjacent outputs share a 4x6 tap
// region. reflect pad (1,2), separable [1,3,3,1]/8, HWC4.
// ---------------------------------------------------------------------------
template <int Si>
__device__ __forceinline__ void down_pair(const float4* __restrict__ src,
                                          int oh, int ow0,
                                          float4* o0, float4* o1) {
    const float kk[4] = {0.125f, 0.375f, 0.375f, 0.125f};
    int rr[4], cc[6];
    #pragma unroll
    for (int i = 0; i < 4; i++) {
        int r = 2 * oh - 1 + i;
        r = r < 0 ? -r : r;
        r = r >= Si ? 2 * Si - 2 - r : r;
        rr[i] = r * Si;
    }
    #pragma unroll
    for (int i = 0; i < 6; i++) {
        int c = 2 * ow0 - 1 + i;
        c = c < 0 ? -c : c;
        c = c >= Si ? 2 * Si - 2 - c : c;
        cc[i] = c;
    }
    float4 a0 = make_float4(0.f, 0.f, 0.f, 0.f);
    float4 a1 = make_float4(0.f, 0.f, 0.f, 0.f);
    #pragma unroll
    for (int i = 0; i < 4; i++) {
        float4 v[6];
        #pragma unroll
        for (int j = 0; j < 6; j++) v[j] = __ldg(src + rr[i] + cc[j]);
        #pragma unroll
        for (int j = 0; j < 4; j++) {
            float w = kk[i] * kk[j];
            a0.x += w * v[j].x;     a0.y += w * v[j].y;     a0.z += w * v[j].z;
            a1.x += w * v[j + 2].x; a1.y += w * v[j + 2].y; a1.z += w * v[j + 2].z;
        }
    }
    *o0 = a0; *o1 = a1;
}

// ---------------------------------------------------------------------------
// Kernels 3-5: flat downsample stages, 2 output px per thread,
// per-batch early exit on the level flag.
// ---------------------------------------------------------------------------
__global__ void down0_kernel() {                       // img4 -> pyr1 (lev>0)
    int t = blockIdx.x * blockDim.x + threadIdx.x;     // NB*128*64
    int n = t >> 13;
    if (g_bp[n].lev <= 0.f) return;
    int oh = (t >> 6) & 127, owp = t & 63;
    float4 o0, o1;
    down_pair<256>(g_img4 + (size_t)n * 65536, oh, owp * 2, &o0, &o1);
    float4* d = g_pyr14 + (size_t)n * 16384 + oh * 128 + owp * 2;
    d[0] = o0; d[1] = o1;
}

__global__ void down1_kernel() {                       // pyr1 -> pyr2 (lev>1)
    int t = blockIdx.x * blockDim.x + threadIdx.x;     // NB*64*32
    int n = t >> 11;
    if (g_bp[n].lev <= 1.f) return;
    int oh = (t >> 5) & 63, owp = t & 31;
    float4 o0, o1;
    down_pair<128>(g_pyr14 + (size_t)n * 16384, oh, owp * 2, &o0, &o1);
    float4* d = g_pyr24 + (size_t)n * 4096 + oh * 64 + owp * 2;
    d[0] = o0; d[1] = o1;
}

__global__ void down2_kernel() {                       // pyr2 -> pyr3 (lev>2)
    int t = blockIdx.x * blockDim.x + threadIdx.x;     // NB*32*16
    int n = t >> 9;
    if (g_bp[n].lev <= 2.f) return;
    int oh = (t >> 4) & 31, owp = t & 15;
    float4 o0, o1;
    down_pair<64>(g_pyr24 + (size_t)n * 4096, oh, owp * 2, &o0, &o1);
    float4* d = g_pyr34 + (size_t)n * 1024 + oh * 32 + owp * 2;
    d[0] = o0; d[1] = o1;
}

// ---------------------------------------------------------------------------
// Bilinear sample (border clamp) from an HWC4 plane. One float4 per tap.
// ---------------------------------------------------------------------------
__device__ __forceinline__ void sample4(const float4* __restrict__ base, int S,
                                        float gx, float gy, float wgt,
                                        float* acc) {
    float x = fmaf(gx + 1.f, 0.5f * (float)S, -0.5f);
    float y = fmaf(gy + 1.f, 0.5f * (float)S, -0.5f);
    float xf = floorf(x), yf = floorf(y);
    float tx = x - xf, ty = y - yf;
    int x0 = (int)xf, y0 = (int)yf;
    int x0c = min(max(x0, 0), S - 1);
    int x1c = min(max(x0 + 1, 0), S - 1);
    int y0c = min(max(y0, 0), S - 1);
    int y1c = min(max(y0 + 1, 0), S - 1);
    float w00 = (1.f - tx) * (1.f - ty) * wgt;
    float w01 = tx * (1.f - ty) * wgt;
    float w10 = (1.f - tx) * ty * wgt;
    float w11 = tx * ty * wgt;
    const float4* r0 = base + y0c * S;
    const float4* r1 = base + y1c * S;
    float4 v00 = __ldg(r0 + x0c);
    float4 v01 = __ldg(r0 + x1c);
    float4 v10 = __ldg(r1 + x0c);
    float4 v11 = __ldg(r1 + x1c);
    acc[0] += v00.x * w00 + v01.x * w01 + v10.x * w10 + v11.x * w11;
    acc[1] += v00.y * w00 + v01.y * w01 + v10.y * w10 + v11.y * w11;
    acc[2] += v00.z * w00 + v01.z * w01 + v10.z * w10 + v11.z * w11;
}

// ---------------------------------------------------------------------------
// Kernel 6: grid gen + mipmap warp. 4 px per thread vertically; warp covers
// an 8-wide x 16-tall tile (compact rotated footprint, 2x MLP vs R4).
// ---------------------------------------------------------------------------
__global__ void warp_kernel(float* __restrict__ out,
                            float* __restrict__ grid_out) {
    int n  = blockIdx.z;
    int w  = blockIdx.x * 8 + threadIdx.x;
    int h0 = blockIdx.y * 64 + threadIdx.y * 4;

    BParam bp = g_bp[n];

    float wc  = ((float)w + 0.5f) * (2.f / (float)WW) - 1.f;
    float hc0 = ((float)h0 + 0.5f) * (2.f / (float)HH) - 1.f;
    float dgx = bp.m01 * (2.f / (float)HH);          // per +1 in h
    float dgy = bp.m11 * (2.f / (float)HH);
    float gxb = bp.m00 * wc + bp.m01 * hc0 + bp.m02;
    float gyb = bp.m10 * wc + bp.m11 * hc0 + bp.m12;

    float gx[4], gy[4];
    #pragma unroll
    for (int k = 0; k < 4; k++) {
        gx[k] = gxb + (float)k * dgx;
        gy[k] = gyb + (float)k * dgy;
    }

    {   // grid stores: [n][h][w][2], evict-first (write-once)
        float* gp = grid_out + ((size_t)n * 65536 + (size_t)h0 * 256 + w) * 2;
        #pragma unroll
        for (int k = 0; k < 4; k++)
            __stcs(reinterpret_cast<float2*>(gp + k * 512),
                   make_float2(gx[k], gy[k]));
    }

    int l0 = bp.l0;
    float w1 = bp.w1;
    float wgt0 = 1.f - w1;

    const float4* b0; int s0;
    if (l0 == 0)      { b0 = g_img4  + (size_t)n * 65536; s0 = 256; }
    else if (l0 == 1) { b0 = g_pyr14 + (size_t)n * 16384; s0 = 128; }
    else              { b0 = g_pyr24 + (size_t)n * 4096;  s0 = 64;  }

    const float4* b1 = nullptr; int s1 = 0;
    if (w1 > 0.f) {
        if (l0 == 0)      { b1 = g_pyr14 + (size_t)n * 16384; s1 = 128; }
        else if (l0 == 1) { b1 = g_pyr24 + (size_t)n * 4096;  s1 = 64;  }
        else              { b1 = g_pyr34 + (size_t)n * 1024;  s1 = 32;  }
    }

    float a[4][3];
    #pragma unroll
    for (int k = 0; k < 4; k++) {
        a[k][0] = a[k][1] = a[k][2] = 0.f;
        sample4(b0, s0, gx[k], gy[k], wgt0, a[k]);
    }
    if (b1) {
        #pragma unroll
        for (int k = 0; k < 4; k++)
            sample4(b1, s1, gx[k], gy[k], w1, a[k]);
    }

    float* o = out + (size_t)n * 3 * 65536 + (size_t)h0 * 256 + w;
    #pragma unroll
    for (int k = 0; k < 4; k++) {
        __stcs(o + k * 256,          a[k][0]);
        __stcs(o + 65536 + k * 256,  a[k][1]);
        __stcs(o + 131072 + k * 256, a[k][2]);
    }
}

// ---------------------------------------------------------------------------
extern "C" void kernel_launch(void* const* d_in, const int* in_sizes, int n_in,
                              void* d_out, int out_size) {
    const float* img  = (const float*)d_in[0];
    const float* feat = (const float*)d_in[1];
    const float* lw   = (const float*)d_in[2];
    const float* lb   = (const float*)d_in[3];

    float* base   = (float*)d_out;
    float* out_p  = base;                                   // N*C*H*W
    float* grid_p = base + (size_t)NB * CCH * HH * WW;
    float* mat_p  = grid_p + (size_t)NB * HH * WW * 2;
    float* aff_p  = mat_p + NB * 6;

    params_kernel<<<NB, 128>>>(feat, lw, lb, mat_p, aff_p);
    hwc_kernel<<<NB * 65536 / 4 / 256, 256>>>(img);
    down0_kernel<<<NB * 128 * 64 / 256, 256>>>();
    down1_kernel<<<NB * 64 * 32 / 256, 256>>>();
    down2_kernel<<<NB * 32 * 16 / 256, 256>>>();

    dim3 blk(8, 16);
    dim3 grd(WW / 8, HH / 64, NB);
    warp_kernel<<<grd, blk>>>(out_p, grid_p);
}

// round 6
// speedup vs baseline: 1.0091x; 1.0091x over previous
#include <cuda_runtime.h>

#define NB  64
#define CCH 3
#define HH  256
#define WW  256
#define DD  512

struct BParam { float m00, m01, m02, m10, m11, m12, w1, lev; int l0; };

__device__ BParam g_bp[NB];
// HWC4 (channels interleaved, 4th lane zero) image + pyramid.
__device__ float4 g_img4[NB * 256 * 256];
__device__ float4 g_pyr14[NB * 128 * 128];
__device__ float4 g_pyr24[NB * 64 * 64];
__device__ float4 g_pyr34[NB * 32 * 32];

// ---------------------------------------------------------------------------
// Kernel 1: linear head + affine params. One block per batch, 4 warps.
// ---------------------------------------------------------------------------
__global__ void params_kernel(const float* __restrict__ feat,
                              const float* __restrict__ lw,
                              const float* __restrict__ lb,
                              float* __restrict__ out_mat,
                              float* __restrict__ out_aff) {
    int n = blockIdx.x;
    int warp = threadIdx.x >> 5, lane = threadIdx.x & 31;
    const float* f  = feat + n * DD;
    const float* wr = lw + warp * DD;
    float s = 0.f;
    #pragma unroll 4
    for (int k = lane; k < DD; k += 32) s += f[k] * wr[k];
    #pragma unroll
    for (int o = 16; o; o >>= 1) s += __shfl_xor_sync(0xffffffffu, s, o);
    __shared__ float p[4];
    if (lane == 0) p[warp] = s + lb[warp];
    __syncthreads();
    if (threadIdx.x == 0) {
        float rot = tanhf(p[0]) * 3.14159265358979323846f;
        float sc  = expf(p[1]);
        float sx  = p[2], sy = p[3];
        float cs = cosf(rot), sn = sinf(rot);
        float m00 = sc * cs, m01 = -sc * sn, m10 = sc * sn, m11 = sc * cs;
        float* mo = out_mat + n * 6;
        mo[0] = m00; mo[1] = m01; mo[2] = sx;
        mo[3] = m10; mo[4] = m11; mo[5] = sy;
        float* ao = out_aff + n * 4;
        ao[0] = rot; ao[1] = sc; ao[2] = sx; ao[3] = sy;
        // Affine warp: jacobian constant per batch; H==W -> both column norms
        // equal exactly sc. levels = clip(log2(max(sc,1)), 0, 2.5)
        float level = log2f(fmaxf(sc, 1.f));
        level = fminf(fmaxf(level, 0.f), 2.5f);
        int l0 = (int)level;
        if (l0 > 2) l0 = 2;
        BParam bp;
        bp.m00 = m00; bp.m01 = m01; bp.m02 = sx;
        bp.m10 = m10; bp.m11 = m11; bp.m12 = sy;
        bp.w1 = level - (float)l0; bp.l0 = l0; bp.lev = level;
        g_bp[n] = bp;
    }
}

// ---------------------------------------------------------------------------
// Kernel 2: CHW -> HWC4 transpose of img. 2 pixels/thread, coalesced.
// ---------------------------------------------------------------------------
__global__ void hwc_kernel(const float* __restrict__ img) {
    int t = blockIdx.x * blockDim.x + threadIdx.x;     // over NB*65536/2
    int idx = t * 2;                                   // n*65536 + h*256 + w
    int n = idx >> 16;
    int hw = idx & 65535;
    const float* p = img + (size_t)n * 3 * 65536 + hw;
    float2 r = *reinterpret_cast<const float2*>(p);
    float2 g = *reinterpret_cast<const float2*>(p + 65536);
    float2 b = *reinterpret_cast<const float2*>(p + 131072);
    g_img4[idx]     = make_float4(r.x, g.x, b.x, 0.f);
    g_img4[idx + 1] = make_float4(r.y, g.y, b.y, 0.f);
}

// ---------------------------------------------------------------------------
// Kernel 3: whole pyramid in one launch. Each block owns a 4x4 pyr3 tile
// (= 8x8 pyr2 = 16x16 pyr1), stages a 46x46 img4 halo in smem and computes
// pyr1 (22x22 incl. halo) -> pyr2 (10x10) -> pyr3 (4x4) in-block, storing
// central regions. Reflect pad (1,2) handled via reflected staging: smem
// slot r holds the value at reflect(base+r), so unreflected-index lookups
// return exactly the reflected tap.
// ---------------------------------------------------------------------------
__global__ void pyr_kernel() {
    int b = blockIdx.x;
    int n = b >> 6;
    float lev = g_bp[n].lev;
    if (lev <= 0.f) return;                    // uniform across block

    int tile = b & 63, tpy = tile >> 3, tpx = tile & 7;
    const float kk[4] = {0.125f, 0.375f, 0.375f, 0.125f};

    __shared__ float4 simg[46][47];
    __shared__ float4 sp1[22][23];
    __shared__ float4 sp2[10][11];

    // Stage img halo: global rows/cols IR0..IR0+45, reflected into [0,255].
    int IR0 = 32 * tpy - 7, IC0 = 32 * tpx - 7;
    {
        const float4* img = g_img4 + (size_t)n * 65536;
        for (int i = threadIdx.x; i < 46 * 46; i += 256) {
            int r = i / 46, c = i - r * 46;
            int gr = IR0 + r; gr = gr < 0 ? -gr : (gr >= 256 ? 510 - gr : gr);
            int gc = IC0 + c; gc = gc < 0 ? -gc : (gc >= 256 ? 510 - gc : gc);
            simg[r][c] = __ldg(img + gr * 256 + gc);
        }
    }
    __syncthreads();

    // pyr1 tile: logical rows P1R0..P1R0+21; compute at reflected coords.
    int P1R0 = 16 * tpy - 3, P1C0 = 16 * tpx - 3;
    for (int i = threadIdx.x; i < 22 * 22; i += 256) {
        int r = i / 22, c = i - r * 22;
        int lr = P1R0 + r; lr = lr < 0 ? -lr : (lr >= 128 ? 254 - lr : lr);
        int lc = P1C0 + c; lc = lc < 0 ? -lc : (lc >= 128 ? 254 - lc : lc);
        float4 acc = make_float4(0.f, 0.f, 0.f, 0.f);
        #pragma unroll
        for (int ii = 0; ii < 4; ii++) {
            int tr = 2 * lr - 1 + ii - IR0;
            #pragma unroll
            for (int jj = 0; jj < 4; jj++) {
                int tc = 2 * lc - 1 + jj - IC0;
                float w = kk[ii] * kk[jj];
                float4 v = simg[tr][tc];
                acc.x += w * v.x; acc.y += w * v.y; acc.z += w * v.z;
            }
        }
        sp1[r][c] = acc;
    }
    __syncthreads();

    // Store central 16x16 of pyr1 (logical rows 16*tpy.., sp1 index +3).
    {
        float4* p1 = g_pyr14 + (size_t)n * 16384;
        int r = threadIdx.x >> 4, c = threadIdx.x & 15;
        p1[(16 * tpy + r) * 128 + 16 * tpx + c] = sp1[3 + r][3 + c];
    }
    if (lev <= 1.f) return;

    // pyr2 tile: logical rows P2R0..P2R0+9.
    int P2R0 = 8 * tpy - 1, P2C0 = 8 * tpx - 1;
    for (int i = threadIdx.x; i < 10 * 10; i += 256) {
        int r = i / 10, c = i - r * 10;
        int lr = P2R0 + r; lr = lr < 0 ? -lr : (lr >= 64 ? 126 - lr : lr);
        int lc = P2C0 + c; lc = lc < 0 ? -lc : (lc >= 64 ? 126 - lc : lc);
        float4 acc = make_float4(0.f, 0.f, 0.f, 0.f);
        #pragma unroll
        for (int ii = 0; ii < 4; ii++) {
            int tr = 2 * lr - 1 + ii - P1R0;
            #pragma unroll
            for (int jj = 0; jj < 4; jj++) {
                int tc = 2 * lc - 1 + jj - P1C0;
                float w = kk[ii] * kk[jj];
                float4 v = sp1[tr][tc];
                acc.x += w * v.x; acc.y += w * v.y; acc.z += w * v.z;
            }
        }
        sp2[r][c] = acc;
    }
    __syncthreads();

    // Store central 8x8 of pyr2 (sp2 index +1).
    if (threadIdx.x < 64) {
        float4* p2 = g_pyr24 + (size_t)n * 4096;
        int r = threadIdx.x >> 3, c = threadIdx.x & 7;
        p2[(8 * tpy + r) * 64 + 8 * tpx + c] = sp2[1 + r][1 + c];
    }
    if (lev <= 2.f) return;

    // pyr3 4x4: outputs always interior-valid; taps span exactly sp2.
    if (threadIdx.x < 16) {
        int r = threadIdx.x >> 2, c = threadIdx.x & 3;
        int m = 4 * tpy + r, mc = 4 * tpx + c;
        float4 acc = make_float4(0.f, 0.f, 0.f, 0.f);
        #pragma unroll
        for (int ii = 0; ii < 4; ii++) {
            int tr = 2 * m - 1 + ii - P2R0;
            #pragma unroll
            for (int jj = 0; jj < 4; jj++) {
                int tc = 2 * mc - 1 + jj - P2C0;
                float w = kk[ii] * kk[jj];
                float4 v = sp2[tr][tc];
                acc.x += w * v.x; acc.y += w * v.y; acc.z += w * v.z;
            }
        }
        g_pyr34[(size_t)n * 1024 + m * 32 + mc] = acc;
    }
}

// ---------------------------------------------------------------------------
// Bilinear sample (border clamp) from an HWC4 plane. One float4 per tap.
// ---------------------------------------------------------------------------
__device__ __forceinline__ void sample4(const float4* __restrict__ base, int S,
                                        float gx, float gy, float wgt,
                                        float* acc) {
    float x = fmaf(gx + 1.f, 0.5f * (float)S, -0.5f);
    float y = fmaf(gy + 1.f, 0.5f * (float)S, -0.5f);
    float xf = floorf(x), yf = floorf(y);
    float tx = x - xf, ty = y - yf;
    int x0 = (int)xf, y0 = (int)yf;
    int x0c = min(max(x0, 0), S - 1);
    int x1c = min(max(x0 + 1, 0), S - 1);
    int y0c = min(max(y0, 0), S - 1);
    int y1c = min(max(y0 + 1, 0), S - 1);
    float w00 = (1.f - tx) * (1.f - ty) * wgt;
    float w01 = tx * (1.f - ty) * wgt;
    float w10 = (1.f - tx) * ty * wgt;
    float w11 = tx * ty * wgt;
    const float4* r0 = base + y0c * S;
    const float4* r1 = base + y1c * S;
    float4 v00 = __ldg(r0 + x0c);
    float4 v01 = __ldg(r0 + x1c);
    float4 v10 = __ldg(r1 + x0c);
    float4 v11 = __ldg(r1 + x1c);
    acc[0] += v00.x * w00 + v01.x * w01 + v10.x * w10 + v11.x * w11;
    acc[1] += v00.y * w00 + v01.y * w01 + v10.y * w10 + v11.y * w11;
    acc[2] += v00.z * w00 + v01.z * w01 + v10.z * w10 + v11.z * w11;
}

// ---------------------------------------------------------------------------
// Kernel 4: grid gen + mipmap warp. Warp covers an 8x8 pixel tile
// (blockDim 8x16, 2 px per thread vertically) — R4 configuration.
// ---------------------------------------------------------------------------
__global__ void warp_kernel(float* __restrict__ out,
                            float* __restrict__ grid_out) {
    int n  = blockIdx.z;
    int w  = blockIdx.x * 8 + threadIdx.x;
    int h0 = blockIdx.y * 32 + threadIdx.y * 2;

    BParam bp = g_bp[n];

    float wc  = ((float)w + 0.5f) * (2.f / (float)WW) - 1.f;
    float hc0 = ((float)h0 + 0.5f) * (2.f / (float)HH) - 1.f;
    float dgx = bp.m01 * (2.f / (float)HH);          // per +1 in h
    float dgy = bp.m11 * (2.f / (float)HH);
    float gx0 = bp.m00 * wc + bp.m01 * hc0 + bp.m02;
    float gy0 = bp.m10 * wc + bp.m11 * hc0 + bp.m12;
    float gx1 = gx0 + dgx;
    float gy1 = gy0 + dgy;

    {   // grid stores: [n][h][w][2], evict-first (write-once)
        float* gp = grid_out + ((size_t)n * 65536 + (size_t)h0 * 256 + w) * 2;
        __stcs(reinterpret_cast<float2*>(gp),       make_float2(gx0, gy0));
        __stcs(reinterpret_cast<float2*>(gp + 512), make_float2(gx1, gy1));
    }

    int l0 = bp.l0;
    float w1 = bp.w1;
    float wgt0 = 1.f - w1;

    const float4* b0; int s0;
    if (l0 == 0)      { b0 = g_img4  + (size_t)n * 65536; s0 = 256; }
    else if (l0 == 1) { b0 = g_pyr14 + (size_t)n * 16384; s0 = 128; }
    else              { b0 = g_pyr24 + (size_t)n * 4096;  s0 = 64;  }

    const float4* b1 = nullptr; int s1 = 0;
    if (w1 > 0.f) {
        if (l0 == 0)      { b1 = g_pyr14 + (size_t)n * 16384; s1 = 128; }
        else if (l0 == 1) { b1 = g_pyr24 + (size_t)n * 4096;  s1 = 64;  }
        else              { b1 = g_pyr34 + (size_t)n * 1024;  s1 = 32;  }
    }

    float a0[3] = {0.f, 0.f, 0.f};
    float a1[3] = {0.f, 0.f, 0.f};
    sample4(b0, s0, gx0, gy0, wgt0, a0);
    sample4(b0, s0, gx1, gy1, wgt0, a1);
    if (b1) {
        sample4(b1, s1, gx0, gy0, w1, a0);
        sample4(b1, s1, gx1, gy1, w1, a1);
    }

    float* o = out + (size_t)n * 3 * 65536 + (size_t)h0 * 256 + w;
    __stcs(o,              a0[0]);
    __stcs(o + 65536,      a0[1]);
    __stcs(o + 131072,     a0[2]);
    __stcs(o + 256,        a1[0]);
    __stcs(o + 65536+256,  a1[1]);
    __stcs(o + 131072+256, a1[2]);
}

// ---------------------------------------------------------------------------
extern "C" void kernel_launch(void* const* d_in, const int* in_sizes, int n_in,
                              void* d_out, int out_size) {
    const float* img  = (const float*)d_in[0];
    const float* feat = (const float*)d_in[1];
    const float* lw   = (const float*)d_in[2];
    const float* lb   = (const float*)d_in[3];

    float* base   = (float*)d_out;
    float* out_p  = base;                                   // N*C*H*W
    float* grid_p = base + (size_t)NB * CCH * HH * WW;
    float* mat_p  = grid_p + (size_t)NB * HH * WW * 2;
    float* aff_p  = mat_p + NB * 6;

    params_kernel<<<NB, 128>>>(feat, lw, lb, mat_p, aff_p);
    hwc_kernel<<<NB * 65536 / 2 / 256, 256>>>(img);
    pyr_kernel<<<NB * 64, 256>>>();

    dim3 blk(8, 16);
    dim3 grd(WW / 8, HH / 32, NB);
    warp_kernel<<<grd, blk>>>(out_p, grid_p);
}

// round 7
// speedup vs baseline: 1.5124x; 1.4988x over previous
#include <cuda_runtime.h>
#include <cuda_fp16.h>

#define NB  64
#define CCH 3
#define HH  256
#define WW  256
#define DD  512

struct BParam { float m00, m01, m02, m10, m11, m12, w1, lev; int l0; };

__device__ BParam g_bp[NB];

// HWC4 fp16 texels: uint2 = {half2(r,g), half2(b,0)} = 8 bytes/px.
__device__ __align__(16) uint2 g_img4[NB * 256 * 256];
__device__ __align__(16) uint2 g_pyr14[NB * 128 * 128];
__device__ __align__(16) uint2 g_pyr24[NB * 64 * 64];
__device__ __align__(16) uint2 g_pyr34[NB * 32 * 32];

__device__ __forceinline__ float3 h4_to_f3(uint2 v) {
    __half2 rg = *reinterpret_cast<__half2*>(&v.x);
    __half2 bz = *reinterpret_cast<__half2*>(&v.y);
    float2 f0 = __half22float2(rg);
    float2 f1 = __half22float2(bz);
    return make_float3(f0.x, f0.y, f1.x);
}
__device__ __forceinline__ uint2 f3_to_h4(float r, float g, float b) {
    __half2 rg = __floats2half2_rn(r, g);
    __half2 bz = __floats2half2_rn(b, 0.f);
    uint2 o;
    o.x = *reinterpret_cast<unsigned*>(&rg);
    o.y = *reinterpret_cast<unsigned*>(&bz);
    return o;
}

// ---------------------------------------------------------------------------
// Kernel 1: linear head + affine params. One block per batch, 4 warps.
// ---------------------------------------------------------------------------
__global__ void params_kernel(const float* __restrict__ feat,
                              const float* __restrict__ lw,
                              const float* __restrict__ lb,
                              float* __restrict__ out_mat,
                              float* __restrict__ out_aff) {
    int n = blockIdx.x;
    int warp = threadIdx.x >> 5, lane = threadIdx.x & 31;
    const float* f  = feat + n * DD;
    const float* wr = lw + warp * DD;
    float s = 0.f;
    #pragma unroll 4
    for (int k = lane; k < DD; k += 32) s += f[k] * wr[k];
    #pragma unroll
    for (int o = 16; o; o >>= 1) s += __shfl_xor_sync(0xffffffffu, s, o);
    __shared__ float p[4];
    if (lane == 0) p[warp] = s + lb[warp];
    __syncthreads();
    if (threadIdx.x == 0) {
        float rot = tanhf(p[0]) * 3.14159265358979323846f;
        float sc  = expf(p[1]);
        float sx  = p[2], sy = p[3];
        float cs = cosf(rot), sn = sinf(rot);
        float m00 = sc * cs, m01 = -sc * sn, m10 = sc * sn, m11 = sc * cs;
        float* mo = out_mat + n * 6;
        mo[0] = m00; mo[1] = m01; mo[2] = sx;
        mo[3] = m10; mo[4] = m11; mo[5] = sy;
        float* ao = out_aff + n * 4;
        ao[0] = rot; ao[1] = sc; ao[2] = sx; ao[3] = sy;
        // Affine warp: jacobian constant per batch; H==W -> both column norms
        // equal exactly sc. levels = clip(log2(max(sc,1)), 0, 2.5)
        float level = log2f(fmaxf(sc, 1.f));
        level = fminf(fmaxf(level, 0.f), 2.5f);
        int l0 = (int)level;
        if (l0 > 2) l0 = 2;
        BParam bp;
        bp.m00 = m00; bp.m01 = m01; bp.m02 = sx;
        bp.m10 = m10; bp.m11 = m11; bp.m12 = sy;
        bp.w1 = level - (float)l0; bp.l0 = l0; bp.lev = level;
        g_bp[n] = bp;
    }
}

// ---------------------------------------------------------------------------
// Kernel 2: CHW fp32 -> HWC4 fp16. 4 px/thread, float4 reads, uint4 stores.
// ---------------------------------------------------------------------------
__global__ void hwc_kernel(const float* __restrict__ img) {
    int t = blockIdx.x * blockDim.x + threadIdx.x;     // over NB*65536/4
    int idx = t * 4;                                   // n*65536 + h*256 + w
    int n = idx >> 16;
    int hw = idx & 65535;
    const float* p = img + (size_t)n * 3 * 65536 + hw;
    float4 r = *reinterpret_cast<const float4*>(p);
    float4 g = *reinterpret_cast<const float4*>(p + 65536);
    float4 b = *reinterpret_cast<const float4*>(p + 131072);
    uint2 o0 = f3_to_h4(r.x, g.x, b.x);
    uint2 o1 = f3_to_h4(r.y, g.y, b.y);
    uint2 o2 = f3_to_h4(r.z, g.z, b.z);
    uint2 o3 = f3_to_h4(r.w, g.w, b.w);
    uint4* dst = reinterpret_cast<uint4*>(g_img4 + idx);
    dst[0] = make_uint4(o0.x, o0.y, o1.x, o1.y);
    dst[1] = make_uint4(o2.x, o2.y, o3.x, o3.y);
}

// ---------------------------------------------------------------------------
// Downsample tap: reflect pad (1,2), 4x4 stride-2 separable [1,3,3,1]/8.
// ---------------------------------------------------------------------------
template <int Si>
__device__ __forceinline__ uint2 down_tap(const uint2* __restrict__ src,
                                          int oh, int ow) {
    const float kk[4] = {0.125f, 0.375f, 0.375f, 0.125f};
    int rr[4], cc[4];
    #pragma unroll
    for (int i = 0; i < 4; i++) {
        int r = 2 * oh - 1 + i;
        r = r < 0 ? -r : r;
        r = r >= Si ? 2 * Si - 2 - r : r;
        rr[i] = r * Si;
        int c = 2 * ow - 1 + i;
        c = c < 0 ? -c : c;
        c = c >= Si ? 2 * Si - 2 - c : c;
        cc[i] = c;
    }
    float ax = 0.f, ay = 0.f, az = 0.f;
    #pragma unroll
    for (int i = 0; i < 4; i++) {
        #pragma unroll
        for (int j = 0; j < 4; j++) {
            float w = kk[i] * kk[j];
            float3 v = h4_to_f3(__ldg(src + rr[i] + cc[j]));
            ax += w * v.x; ay += w * v.y; az += w * v.z;
        }
    }
    return f3_to_h4(ax, ay, az);
}

// ---------------------------------------------------------------------------
// Kernels 3-5: flat downsample stages (R4 config: 1 px/thread), per-batch
// early exit on the level flag.
// ---------------------------------------------------------------------------
__global__ void down0_kernel() {                       // img4 -> pyr1 (lev>0)
    int idx = blockIdx.x * blockDim.x + threadIdx.x;   // n*16384 + oh*128 + ow
    int n = idx >> 14;
    if (g_bp[n].lev <= 0.f) return;
    g_pyr14[idx] = down_tap<256>(g_img4 + (size_t)n * 65536,
                                 (idx >> 7) & 127, idx & 127);
}

__global__ void down1_kernel() {                       // pyr1 -> pyr2 (lev>1)
    int idx = blockIdx.x * blockDim.x + threadIdx.x;   // n*4096 + oh*64 + ow
    int n = idx >> 12;
    if (g_bp[n].lev <= 1.f) return;
    g_pyr24[idx] = down_tap<128>(g_pyr14 + (size_t)n * 16384,
                                 (idx >> 6) & 63, idx & 63);
}

__global__ void down2_kernel() {                       // pyr2 -> pyr3 (lev>2)
    int idx = blockIdx.x * blockDim.x + threadIdx.x;   // n*1024 + oh*32 + ow
    int n = idx >> 10;
    if (g_bp[n].lev <= 2.f) return;
    g_pyr34[idx] = down_tap<64>(g_pyr24 + (size_t)n * 4096,
                                (idx >> 5) & 31, idx & 31);
}

// ---------------------------------------------------------------------------
// Bilinear sample (border clamp) from an HWC4-fp16 plane. One uint2 per tap.
// ---------------------------------------------------------------------------
__device__ __forceinline__ void sample4(const uint2* __restrict__ base, int S,
                                        float gx, float gy, float wgt,
                                        float* acc) {
    float x = fmaf(gx + 1.f, 0.5f * (float)S, -0.5f);
    float y = fmaf(gy + 1.f, 0.5f * (float)S, -0.5f);
    float xf = floorf(x), yf = floorf(y);
    float tx = x - xf, ty = y - yf;
    int x0 = (int)xf, y0 = (int)yf;
    int x0c = min(max(x0, 0), S - 1);
    int x1c = min(max(x0 + 1, 0), S - 1);
    int y0c = min(max(y0, 0), S - 1);
    int y1c = min(max(y0 + 1, 0), S - 1);
    float w00 = (1.f - tx) * (1.f - ty) * wgt;
    float w01 = tx * (1.f - ty) * wgt;
    float w10 = (1.f - tx) * ty * wgt;
    float w11 = tx * ty * wgt;
    const uint2* r0 = base + y0c * S;
    const uint2* r1 = base + y1c * S;
    float3 v00 = h4_to_f3(__ldg(r0 + x0c));
    float3 v01 = h4_to_f3(__ldg(r0 + x1c));
    float3 v10 = h4_to_f3(__ldg(r1 + x0c));
    float3 v11 = h4_to_f3(__ldg(r1 + x1c));
    acc[0] += v00.x * w00 + v01.x * w01 + v10.x * w10 + v11.x * w11;
    acc[1] += v00.y * w00 + v01.y * w01 + v10.y * w10 + v11.y * w11;
    acc[2] += v00.z * w00 + v01.z * w01 + v10.z * w10 + v11.z * w11;
}

// ---------------------------------------------------------------------------
// Kernel 6: grid gen + mipmap warp. Warp covers an 8x8 pixel tile
// (blockDim 8x16, 2 px per thread vertically) — R4 configuration.
// ---------------------------------------------------------------------------
__global__ void warp_kernel(float* __restrict__ out,
                            float* __restrict__ grid_out) {
    int n  = blockIdx.z;
    int w  = blockIdx.x * 8 + threadIdx.x;
    int h0 = blockIdx.y * 32 + threadIdx.y * 2;

    BParam bp = g_bp[n];

    float wc  = ((float)w + 0.5f) * (2.f / (float)WW) - 1.f;
    float hc0 = ((float)h0 + 0.5f) * (2.f / (float)HH) - 1.f;
    float dgx = bp.m01 * (2.f / (float)HH);          // per +1 in h
    float dgy = bp.m11 * (2.f / (float)HH);
    float gx0 = bp.m00 * wc + bp.m01 * hc0 + bp.m02;
    float gy0 = bp.m10 * wc + bp.m11 * hc0 + bp.m12;
    float gx1 = gx0 + dgx;
    float gy1 = gy0 + dgy;

    {   // grid stores: [n][h][w][2], evict-first (write-once)
        float* gp = grid_out + ((size_t)n * 65536 + (size_t)h0 * 256 + w) * 2;
        __stcs(reinterpret_cast<float2*>(gp),       make_float2(gx0, gy0));
        __stcs(reinterpret_cast<float2*>(gp + 512), make_float2(gx1, gy1));
    }

    int l0 = bp.l0;
    float w1 = bp.w1;
    float wgt0 = 1.f - w1;

    const uint2* b0; int s0;
    if (l0 == 0)      { b0 = g_img4  + (size_t)n * 65536; s0 = 256; }
    else if (l0 == 1) { b0 = g_pyr14 + (size_t)n * 16384; s0 = 128; }
    else              { b0 = g_pyr24 + (size_t)n * 4096;  s0 = 64;  }

    const uint2* b1 = nullptr; int s1 = 0;
    if (w1 > 0.f) {
        if (l0 == 0)      { b1 = g_pyr14 + (size_t)n * 16384; s1 = 128; }
        else if (l0 == 1) { b1 = g_pyr24 + (size_t)n * 4096;  s1 = 64;  }
        else              { b1 = g_pyr34 + (size_t)n * 1024;  s1 = 32;  }
    }

    float a0[3] = {0.f, 0.f, 0.f};
    float a1[3] = {0.f, 0.f, 0.f};
    sample4(b0, s0, gx0, gy0, wgt0, a0);
    sample4(b0, s0, gx1, gy1, wgt0, a1);
    if (b1) {
        sample4(b1, s1, gx0, gy0, w1, a0);
        sample4(b1, s1, gx1, gy1, w1, a1);
    }

    float* o = out + (size_t)n * 3 * 65536 + (size_t)h0 * 256 + w;
    __stcs(o,              a0[0]);
    __stcs(o + 65536,      a0[1]);
    __stcs(o + 131072,     a0[2]);
    __stcs(o + 256,        a1[0]);
    __stcs(o + 65536+256,  a1[1]);
    __stcs(o + 131072+256, a1[2]);
}

// ---------------------------------------------------------------------------
extern "C" void kernel_launch(void* const* d_in, const int* in_sizes, int n_in,
                              void* d_out, int out_size) {
    const float* img  = (const float*)d_in[0];
    const float* feat = (const float*)d_in[1];
    const float* lw   = (const float*)d_in[2];
    const float* lb   = (const float*)d_in[3];

    float* base   = (float*)d_out;
    float* out_p  = base;                                   // N*C*H*W
    float* grid_p = base + (size_t)NB * CCH * HH * WW;
    float* mat_p  = grid_p + (size_t)NB * HH * WW * 2;
    float* aff_p  = mat_p + NB * 6;

    params_kernel<<<NB, 128>>>(feat, lw, lb, mat_p, aff_p);
    hwc_kernel<<<NB * 65536 / 4 / 256, 256>>>(img);
    down0_kernel<<<NB * 16384 / 256, 256>>>();
    down1_kernel<<<NB * 4096 / 256, 256>>>();
    down2_kernel<<<NB * 1024 / 256, 256>>>();

    dim3 blk(8, 16);
    dim3 grd(WW / 8, HH / 32, NB);
    warp_kernel<<<grd, blk>>>(out_p, grid_p);
}

// round 9
// speedup vs baseline: 1.5176x; 1.0034x over previous
#include <cuda_runtime.h>
#include <cuda_fp16.h>

#define NB  64
#define CCH 3
#define HH  256
#define WW  256
#define DD  512

struct BParam { float m00, m01, m02, m10, m11, m12, w1, lev; int l0; };

__device__ BParam g_bp[NB];

// HWC4 fp16 texels: uint2 = {half2(r,g), half2(b,0)} = 8 bytes/px.
__device__ __align__(16) uint2 g_img4[NB * 256 * 256];
__device__ __align__(16) uint2 g_pyr14[NB * 128 * 128];
__device__ __align__(16) uint2 g_pyr24[NB * 64 * 64];
__device__ __align__(16) uint2 g_pyr34[NB * 32 * 32];

__device__ __forceinline__ float3 h4_to_f3(uint2 v) {
    __half2 rg = *reinterpret_cast<__half2*>(&v.x);
    __half2 bz = *reinterpret_cast<__half2*>(&v.y);
    float2 f0 = __half22float2(rg);
    float2 f1 = __half22float2(bz);
    return make_float3(f0.x, f0.y, f1.x);
}
__device__ __forceinline__ uint2 f3_to_h4(float r, float g, float b) {
    __half2 rg = __floats2half2_rn(r, g);
    __half2 bz = __floats2half2_rn(b, 0.f);
    uint2 o;
    o.x = *reinterpret_cast<unsigned*>(&rg);
    o.y = *reinterpret_cast<unsigned*>(&bz);
    return o;
}
__device__ __forceinline__ int refl(int v, int S) {
    v = v < 0 ? -v : v;
    return v >= S ? 2 * S - 2 - v : v;
}

// ---------------------------------------------------------------------------
// Kernel 1: linear head + affine params. One block per batch, 4 warps.
// ---------------------------------------------------------------------------
__global__ void params_kernel(const float* __restrict__ feat,
                              const float* __restrict__ lw,
                              const float* __restrict__ lb,
                              float* __restrict__ out_mat,
                              float* __restrict__ out_aff) {
    int n = blockIdx.x;
    int warp = threadIdx.x >> 5, lane = threadIdx.x & 31;
    const float* f  = feat + n * DD;
    const float* wr = lw + warp * DD;
    float s = 0.f;
    #pragma unroll 4
    for (int k = lane; k < DD; k += 32) s += f[k] * wr[k];
    #pragma unroll
    for (int o = 16; o; o >>= 1) s += __shfl_xor_sync(0xffffffffu, s, o);
    __shared__ float p[4];
    if (lane == 0) p[warp] = s + lb[warp];
    __syncthreads();
    if (threadIdx.x == 0) {
        float rot = tanhf(p[0]) * 3.14159265358979323846f;
        float sc  = expf(p[1]);
        float sx  = p[2], sy = p[3];
        float cs = cosf(rot), sn = sinf(rot);
        float m00 = sc * cs, m01 = -sc * sn, m10 = sc * sn, m11 = sc * cs;
        float* mo = out_mat + n * 6;
        mo[0] = m00; mo[1] = m01; mo[2] = sx;
        mo[3] = m10; mo[4] = m11; mo[5] = sy;
        float* ao = out_aff + n * 4;
        ao[0] = rot; ao[1] = sc; ao[2] = sx; ao[3] = sy;
        // Affine warp: jacobian constant per batch; H==W -> both column norms
        // equal exactly sc. levels = clip(log2(max(sc,1)), 0, 2.5)
        float level = log2f(fmaxf(sc, 1.f));
        level = fminf(fmaxf(level, 0.f), 2.5f);
        int l0 = (int)level;
        if (l0 > 2) l0 = 2;
        BParam bp;
        bp.m00 = m00; bp.m01 = m01; bp.m02 = sx;
        bp.m10 = m10; bp.m11 = m11; bp.m12 = sy;
        bp.w1 = level - (float)l0; bp.l0 = l0; bp.lev = level;
        g_bp[n] = bp;
    }
}

// ---------------------------------------------------------------------------
// Kernel 2: fused CHW->HWC4-fp16 transpose + down0. Block = 32x8 img tile.
// Phase 1: convert & store img4 (also into smem). Phase 2 (lev>0, uniform
// per block): stage 84-texel reflected halo, compute 16x4 pyr1 tile from
// smem. Smem slot r holds img[reflect(R0+r)] so tap lookups are exact.
// ---------------------------------------------------------------------------
__global__ void hwc0_kernel(const float* __restrict__ img) {
    int bx = blockIdx.x & 7;
    int by = (blockIdx.x >> 3) & 31;
    int n  = blockIdx.x >> 8;
    int tx = threadIdx.x & 31, ty = threadIdx.x >> 5;
    int R0 = by * 8, C0 = bx * 32;

    __shared__ uint2 st[10][35];        // rows -1..8, cols -1..33 (34 used)

    const float* p = img + (size_t)n * 3 * 65536 + (R0 + ty) * 256 + C0 + tx;
    float r = __ldg(p), g = __ldg(p + 65536), b = __ldg(p + 131072);
    uint2 t = f3_to_h4(r, g, b);
    g_img4[(size_t)n * 65536 + (R0 + ty) * 256 + C0 + tx] = t;

    if (g_bp[n].lev <= 0.f) return;     // uniform per block

    st[ty + 1][tx + 1] = t;

    // Halo: rows -1 & 8 (34 cols each), cols -1 & 32 for rows 0..7. 84 texels.
    int i = threadIdx.x;
    if (i < 84) {
        int hr, hc;
        if (i < 34)       { hr = -1; hc = i - 1; }
        else if (i < 68)  { hr = 8;  hc = i - 35; }
        else              { hr = (i - 68) >> 1; hc = ((i - 68) & 1) ? 32 : -1; }
        int gr = refl(R0 + hr, 256);
        int gc = refl(C0 + hc, 256);
        const float* q = img + (size_t)n * 3 * 65536 + gr * 256 + gc;
        st[hr + 1][hc + 1] = f3_to_h4(__ldg(q), __ldg(q + 65536), __ldg(q + 131072));
    }
    __syncthreads();

    // pyr1 tile 16 wide x 4 tall at (4*by, 16*bx). Threads 0..63.
    if (threadIdx.x < 64) {
        int ow = threadIdx.x & 15, oh = threadIdx.x >> 4;
        const float kk[4] = {0.125f, 0.375f, 0.375f, 0.125f};
        float ax = 0.f, ay = 0.f, az = 0.f;
        #pragma unroll
        for (int ii = 0; ii < 4; ii++) {
            int sr = 2 * oh + ii;               // local tap row + 1 offset
            #pragma unroll
            for (int jj = 0; jj < 4; jj++) {
                int sc = 2 * ow + jj;           // local tap col + 1 offset
                float w = kk[ii] * kk[jj];
                float3 v = h4_to_f3(st[sr][sc]);
                ax += w * v.x; ay += w * v.y; az += w * v.z;
            }
        }
        g_pyr14[(size_t)n * 16384 + (4 * by + oh) * 128 + 16 * bx + ow] =
            f3_to_h4(ax, ay, az);
    }
}

// ---------------------------------------------------------------------------
// Downsample tap (global source): reflect pad (1,2), separable [1,3,3,1]/8.
// ---------------------------------------------------------------------------
template <int Si>
__device__ __forceinline__ uint2 down_tap(const uint2* __restrict__ src,
                                          int oh, int ow) {
    const float kk[4] = {0.125f, 0.375f, 0.375f, 0.125f};
    int rr[4], cc[4];
    #pragma unroll
    for (int i = 0; i < 4; i++) {
        rr[i] = refl(2 * oh - 1 + i, Si) * Si;
        cc[i] = refl(2 * ow - 1 + i, Si);
    }
    float ax = 0.f, ay = 0.f, az = 0.f;
    #pragma unroll
    for (int i = 0; i < 4; i++) {
        #pragma unroll
        for (int j = 0; j < 4; j++) {
            float w = kk[i] * kk[j];
            float3 v = h4_to_f3(__ldg(src + rr[i] + cc[j]));
            ax += w * v.x; ay += w * v.y; az += w * v.z;
        }
    }
    return f3_to_h4(ax, ay, az);
}

// ---------------------------------------------------------------------------
// Kernel 3: down1 + down2 in ONE launch. blockIdx.y = batch.
// j < 4096: pyr2 from pyr1 (lev>1). j >= 4096: pyr3 computed DIRECTLY from
// pyr1 via on-the-fly composed two-stage taps (no dependency on this
// kernel's pyr2 writes) — only for lev>2 batches (~0.1%).
// ---------------------------------------------------------------------------
__global__ void down12_kernel() {
    int n = blockIdx.y;
    float lev = g_bp[n].lev;
    int j = blockIdx.x * blockDim.x + threadIdx.x;    // 0..5119

    if (j < 4096) {
        if (lev <= 1.f) return;
        g_pyr24[(size_t)n * 4096 + j] =
            down_tap<128>(g_pyr14 + (size_t)n * 16384, j >> 6, j & 63);
    } else {
        if (lev <= 2.f) return;
        int j2 = j - 4096;
        int oh = j2 >> 5, ow = j2 & 31;
        const uint2* p1 = g_pyr14 + (size_t)n * 16384;
        const float kk[4] = {0.125f, 0.375f, 0.375f, 0.125f};
        float ax = 0.f, ay = 0.f, az = 0.f;
        #pragma unroll
        for (int ii = 0; ii < 4; ii++) {
            int r2 = refl(2 * oh - 1 + ii, 64);
            #pragma unroll
            for (int jj = 0; jj < 4; jj++) {
                int c2 = refl(2 * ow - 1 + jj, 64);
                float w = kk[ii] * kk[jj];
                float3 v = h4_to_f3(down_tap<128>(p1, r2, c2));
                ax += w * v.x; ay += w * v.y; az += w * v.z;
            }
        }
        g_pyr34[(size_t)n * 1024 + j2] = f3_to_h4(ax, ay, az);
    }
}

// ---------------------------------------------------------------------------
// Bilinear sample (border clamp) from an HWC4-fp16 plane. One uint2 per tap.
// ---------------------------------------------------------------------------
__device__ __forceinline__ void sample4(const uint2* __restrict__ base, int S,
                                        float gx, float gy, float wgt,
                                        float* acc) {
    float x = fmaf(gx + 1.f, 0.5f * (float)S, -0.5f);
    float y = fmaf(gy + 1.f, 0.5f * (float)S, -0.5f);
    float xf = floorf(x), yf = floorf(y);
    float tx = x - xf, ty = y - yf;
    int x0 = (int)xf, y0 = (int)yf;
    int x0c = min(max(x0, 0), S - 1);
    int x1c = min(max(x0 + 1, 0), S - 1);
    int y0c = min(max(y0, 0), S - 1);
    int y1c = min(max(y0 + 1, 0), S - 1);
    float w00 = (1.f - tx) * (1.f - ty) * wgt;
    float w01 = tx * (1.f - ty) * wgt;
    float w10 = (1.f - tx) * ty * wgt;
    float w11 = tx * ty * wgt;
    const uint2* r0 = base + y0c * S;
    const uint2* r1 = base + y1c * S;
    float3 v00 = h4_to_f3(__ldg(r0 + x0c));
    float3 v01 = h4_to_f3(__ldg(r0 + x1c));
    float3 v10 = h4_to_f3(__ldg(r1 + x0c));
    float3 v11 = h4_to_f3(__ldg(r1 + x1c));
    acc[0] += v00.x * w00 + v01.x * w01 + v10.x * w10 + v11.x * w11;
    acc[1] += v00.y * w00 + v01.y * w01 + v10.y * w10 + v11.y * w11;
    acc[2] += v00.z * w00 + v01.z * w01 + v10.z * w10 + v11.z * w11;
}

// ---------------------------------------------------------------------------
// Kernel 4: grid gen + mipmap warp. Warp covers an 8x8 pixel tile
// (blockDim 8x16, 2 px per thread vertically) — known-good configuration.
// ---------------------------------------------------------------------------
__global__ void warp_kernel(float* __restrict__ out,
                            float* __restrict__ grid_out) {
    int n  = blockIdx.z;
    int w  = blockIdx.x * 8 + threadIdx.x;
    int h0 = blockIdx.y * 32 + threadIdx.y * 2;

    BParam bp = g_bp[n];

    float wc  = ((float)w + 0.5f) * (2.f / (float)WW) - 1.f;
    float hc0 = ((float)h0 + 0.5f) * (2.f / (float)HH) - 1.f;
    float dgx = bp.m01 * (2.f / (float)HH);          // per +1 in h
    float dgy = bp.m11 * (2.f / (float)HH);
    float gx0 = bp.m00 * wc + bp.m01 * hc0 + bp.m02;
    float gy0 = bp.m10 * wc + bp.m11 * hc0 + bp.m12;
    float gx1 = gx0 + dgx;
    float gy1 = gy0 + dgy;

    {   // grid stores: [n][h][w][2], evict-first (write-once)
        float* gp = grid_out + ((size_t)n * 65536 + (size_t)h0 * 256 + w) * 2;
        __stcs(reinterpret_cast<float2*>(gp),       make_float2(gx0, gy0));
        __stcs(reinterpret_cast<float2*>(gp + 512), make_float2(gx1, gy1));
    }

    int l0 = bp.l0;
    float w1 = bp.w1;
    float wgt0 = 1.f - w1;

    const uint2* b0; int s0;
    if (l0 == 0)      { b0 = g_img4  + (size_t)n * 65536; s0 = 256; }
    else if (l0 == 1) { b0 = g_pyr14 + (size_t)n * 16384; s0 = 128; }
    else              { b0 = g_pyr24 + (size_t)n * 4096;  s0 = 64;  }

    const uint2* b1 = nullptr; int s1 = 0;
    if (w1 > 0.f) {
        if (l0 == 0)      { b1 = g_pyr14 + (size_t)n * 16384; s1 = 128; }
        else if (l0 == 1) { b1 = g_pyr24 + (size_t)n * 4096;  s1 = 64;  }
        else              { b1 = g_pyr34 + (size_t)n * 1024;  s1 = 32;  }
    }

    float a0[3] = {0.f, 0.f, 0.f};
    float a1[3] = {0.f, 0.f, 0.f};
    sample4(b0, s0, gx0, gy0, wgt0, a0);
    sample4(b0, s0, gx1, gy1, wgt0, a1);
    if (b1) {
        sample4(b1, s1, gx0, gy0, w1, a0);
        sample4(b1, s1, gx1, gy1, w1, a1);
    }

    float* o = out + (size_t)n * 3 * 65536 + (size_t)h0 * 256 + w;
    __stcs(o,              a0[0]);
    __stcs(o + 65536,      a0[1]);
    __stcs(o + 131072,     a0[2]);
    __stcs(o + 256,        a1[0]);
    __stcs(o + 65536+256,  a1[1]);
    __stcs(o + 131072+256, a1[2]);
}

// ---------------------------------------------------------------------------
extern "C" void kernel_launch(void* const* d_in, const int* in_sizes, int n_in,
                              void* d_out, int out_size) {
    const float* img  = (const float*)d_in[0];
    const float* feat = (const float*)d_in[1];
    const float* lw   = (const float*)d_in[2];
    const float* lb   = (const float*)d_in[3];

    float* base   = (float*)d_out;
    float* out_p  = base;                                   // N*C*H*W
    float* grid_p = base + (size_t)NB * CCH * HH * WW;
    float* mat_p  = grid_p + (size_t)NB * HH * WW * 2;
    float* aff_p  = mat_p + NB * 6;

    params_kernel<<<NB, 128>>>(feat, lw, lb, mat_p, aff_p);
    hwc0_kernel<<<NB * 256, 256>>>(img);                    // transpose + down0
    {
        dim3 g(20, NB);                                     // 5120 threads/batch
        down12_kernel<<<g, 256>>>();
    }

    dim3 blk(8, 16);
    dim3 grd(WW / 8, HH / 32, NB);
    warp_kernel<<<grd, blk>>>(out_p, grid_p);
}

// round 11
// speedup vs baseline: 1.5456x; 1.0184x over previous
#include <cuda_runtime.h>
#include <cuda_fp16.h>

#define NB  64
#define CCH 3
#define HH  256
#define WW  256
#define DD  512

struct BParam { float m00, m01, m02, m10, m11, m12, w1, lev; int l0; };

__device__ BParam g_bp[NB];

// HWC4 fp16 texels: uint2 = {half2(r,g), half2(b,0)} = 8 bytes/px.
__device__ __align__(16) uint2 g_img4[NB * 256 * 256];
__device__ __align__(16) uint2 g_pyr14[NB * 128 * 128];
__device__ __align__(16) uint2 g_pyr24[NB * 64 * 64];
__device__ __align__(16) uint2 g_pyr34[NB * 32 * 32];

__device__ __forceinline__ float3 h4_to_f3(uint2 v) {
    __half2 rg = *reinterpret_cast<__half2*>(&v.x);
    __half2 bz = *reinterpret_cast<__half2*>(&v.y);
    float2 f0 = __half22float2(rg);
    float2 f1 = __half22float2(bz);
    return make_float3(f0.x, f0.y, f1.x);
}
__device__ __forceinline__ uint2 f3_to_h4(float r, float g, float b) {
    __half2 rg = __floats2half2_rn(r, g);
    __half2 bz = __floats2half2_rn(b, 0.f);
    uint2 o;
    o.x = *reinterpret_cast<unsigned*>(&rg);
    o.y = *reinterpret_cast<unsigned*>(&bz);
    return o;
}
__device__ __forceinline__ int refl(int v, int S) {
    v = v < 0 ? -v : v;
    return v >= S ? 2 * S - 2 - v : v;
}

// ---------------------------------------------------------------------------
// Kernel 1: linear head + affine params. One block per batch, 4 warps.
// ---------------------------------------------------------------------------
__global__ void params_kernel(const float* __restrict__ feat,
                              const float* __restrict__ lw,
                              const float* __restrict__ lb,
                              float* __restrict__ out_mat,
                              float* __restrict__ out_aff) {
    int n = blockIdx.x;
    int warp = threadIdx.x >> 5, lane = threadIdx.x & 31;
    const float* f  = feat + n * DD;
    const float* wr = lw + warp * DD;
    float s = 0.f;
    #pragma unroll 4
    for (int k = lane; k < DD; k += 32) s += f[k] * wr[k];
    #pragma unroll
    for (int o = 16; o; o >>= 1) s += __shfl_xor_sync(0xffffffffu, s, o);
    __shared__ float p[4];
    if (lane == 0) p[warp] = s + lb[warp];
    __syncthreads();
    if (threadIdx.x == 0) {
        float rot = tanhf(p[0]) * 3.14159265358979323846f;
        float sc  = expf(p[1]);
        float sx  = p[2], sy = p[3];
        float cs = cosf(rot), sn = sinf(rot);
        float m00 = sc * cs, m01 = -sc * sn, m10 = sc * sn, m11 = sc * cs;
        float* mo = out_mat + n * 6;
        mo[0] = m00; mo[1] = m01; mo[2] = sx;
        mo[3] = m10; mo[4] = m11; mo[5] = sy;
        float* ao = out_aff + n * 4;
        ao[0] = rot; ao[1] = sc; ao[2] = sx; ao[3] = sy;
        // Affine warp: jacobian constant per batch; H==W -> both column norms
        // equal exactly sc. levels = clip(log2(max(sc,1)), 0, 2.5)
        float level = log2f(fmaxf(sc, 1.f));
        level = fminf(fmaxf(level, 0.f), 2.5f);
        int l0 = (int)level;
        if (l0 > 2) l0 = 2;
        BParam bp;
        bp.m00 = m00; bp.m01 = m01; bp.m02 = sx;
        bp.m10 = m10; bp.m11 = m11; bp.m12 = sy;
        bp.w1 = level - (float)l0; bp.l0 = l0; bp.lev = level;
        g_bp[n] = bp;
    }
}

// ---------------------------------------------------------------------------
// Kernel 2: fused CHW->HWC4-fp16 transpose + down0. Block = 32x8 img tile.
// ---------------------------------------------------------------------------
__global__ void hwc0_kernel(const float* __restrict__ img) {
    int bx = blockIdx.x & 7;
    int by = (blockIdx.x >> 3) & 31;
    int n  = blockIdx.x >> 8;
    int tx = threadIdx.x & 31, ty = threadIdx.x >> 5;
    int R0 = by * 8, C0 = bx * 32;

    __shared__ uint2 st[10][35];        // rows -1..8, cols -1..33 (34 used)

    const float* p = img + (size_t)n * 3 * 65536 + (R0 + ty) * 256 + C0 + tx;
    float r = __ldg(p), g = __ldg(p + 65536), b = __ldg(p + 131072);
    uint2 t = f3_to_h4(r, g, b);
    g_img4[(size_t)n * 65536 + (R0 + ty) * 256 + C0 + tx] = t;

    if (g_bp[n].lev <= 0.f) return;     // uniform per block

    st[ty + 1][tx + 1] = t;

    // Halo: rows -1 & 8 (34 cols each), cols -1 & 32 for rows 0..7. 84 texels.
    int i = threadIdx.x;
    if (i < 84) {
        int hr, hc;
        if (i < 34)       { hr = -1; hc = i - 1; }
        else if (i < 68)  { hr = 8;  hc = i - 35; }
        else              { hr = (i - 68) >> 1; hc = ((i - 68) & 1) ? 32 : -1; }
        int gr = refl(R0 + hr, 256);
        int gc = refl(C0 + hc, 256);
        const float* q = img + (size_t)n * 3 * 65536 + gr * 256 + gc;
        st[hr + 1][hc + 1] = f3_to_h4(__ldg(q), __ldg(q + 65536), __ldg(q + 131072));
    }
    __syncthreads();

    // pyr1 tile 16 wide x 4 tall at (4*by, 16*bx). Threads 0..63.
    if (threadIdx.x < 64) {
        int ow = threadIdx.x & 15, oh = threadIdx.x >> 4;
        const float kk[4] = {0.125f, 0.375f, 0.375f, 0.125f};
        float ax = 0.f, ay = 0.f, az = 0.f;
        #pragma unroll
        for (int ii = 0; ii < 4; ii++) {
            int sr = 2 * oh + ii;
            #pragma unroll
            for (int jj = 0; jj < 4; jj++) {
                int sc = 2 * ow + jj;
                float w = kk[ii] * kk[jj];
                float3 v = h4_to_f3(st[sr][sc]);
                ax += w * v.x; ay += w * v.y; az += w * v.z;
            }
        }
        g_pyr14[(size_t)n * 16384 + (4 * by + oh) * 128 + 16 * bx + ow] =
            f3_to_h4(ax, ay, az);
    }
}

// ---------------------------------------------------------------------------
// Downsample tap (global source): reflect pad (1,2), separable [1,3,3,1]/8.
// ---------------------------------------------------------------------------
template <int Si>
__device__ __forceinline__ uint2 down_tap(const uint2* __restrict__ src,
                                          int oh, int ow) {
    const float kk[4] = {0.125f, 0.375f, 0.375f, 0.125f};
    int rr[4], cc[4];
    #pragma unroll
    for (int i = 0; i < 4; i++) {
        rr[i] = refl(2 * oh - 1 + i, Si) * Si;
        cc[i] = refl(2 * ow - 1 + i, Si);
    }
    float ax = 0.f, ay = 0.f, az = 0.f;
    #pragma unroll
    for (int i = 0; i < 4; i++) {
        #pragma unroll
        for (int j = 0; j < 4; j++) {
            float w = kk[i] * kk[j];
            float3 v = h4_to_f3(__ldg(src + rr[i] + cc[j]));
            ax += w * v.x; ay += w * v.y; az += w * v.z;
        }
    }
    return f3_to_h4(ax, ay, az);
}

// ---------------------------------------------------------------------------
// Kernel 3: down1 + down2 in ONE launch. blockIdx.y = batch.
// ---------------------------------------------------------------------------
__global__ void down12_kernel() {
    int n = blockIdx.y;
    float lev = g_bp[n].lev;
    int j = blockIdx.x * blockDim.x + threadIdx.x;    // 0..5119

    if (j < 4096) {
        if (lev <= 1.f) return;
        g_pyr24[(size_t)n * 4096 + j] =
            down_tap<128>(g_pyr14 + (size_t)n * 16384, j >> 6, j & 63);
    } else {
        if (lev <= 2.f) return;
        int j2 = j - 4096;
        int oh = j2 >> 5, ow = j2 & 31;
        const uint2* p1 = g_pyr14 + (size_t)n * 16384;
        const float kk[4] = {0.125f, 0.375f, 0.375f, 0.125f};
        float ax = 0.f, ay = 0.f, az = 0.f;
        #pragma unroll
        for (int ii = 0; ii < 4; ii++) {
            int r2 = refl(2 * oh - 1 + ii, 64);
            #pragma unroll
            for (int jj = 0; jj < 4; jj++) {
                int c2 = refl(2 * ow - 1 + jj, 64);
                float w = kk[ii] * kk[jj];
                float3 v = h4_to_f3(down_tap<128>(p1, r2, c2));
                ax += w * v.x; ay += w * v.y; az += w * v.z;
            }
        }
        g_pyr34[(size_t)n * 1024 + j2] = f3_to_h4(ax, ay, az);
    }
}

// ---------------------------------------------------------------------------
// Bilinear sample (border clamp) from an HWC4-fp16 plane. One uint2 per tap.
// ---------------------------------------------------------------------------
__device__ __forceinline__ void sample4(const uint2* __restrict__ base, int S,
                                        float gx, float gy, float wgt,
                                        float* acc) {
    float x = fmaf(gx + 1.f, 0.5f * (float)S, -0.5f);
    float y = fmaf(gy + 1.f, 0.5f * (float)S, -0.5f);
    float xf = floorf(x), yf = floorf(y);
    float tx = x - xf, ty = y - yf;
    int x0 = (int)xf, y0 = (int)yf;
    int x0c = min(max(x0, 0), S - 1);
    int x1c = min(max(x0 + 1, 0), S - 1);
    int y0c = min(max(y0, 0), S - 1);
    int y1c = min(max(y0 + 1, 0), S - 1);
    float w00 = (1.f - tx) * (1.f - ty) * wgt;
    float w01 = tx * (1.f - ty) * wgt;
    float w10 = (1.f - tx) * ty * wgt;
    float w11 = tx * ty * wgt;
    const uint2* r0 = base + y0c * S;
    const uint2* r1 = base + y1c * S;
    float3 v00 = h4_to_f3(__ldg(r0 + x0c));
    float3 v01 = h4_to_f3(__ldg(r0 + x1c));
    float3 v10 = h4_to_f3(__ldg(r1 + x0c));
    float3 v11 = h4_to_f3(__ldg(r1 + x1c));
    acc[0] += v00.x * w00 + v01.x * w01 + v10.x * w10 + v11.x * w11;
    acc[1] += v00.y * w00 + v01.y * w01 + v10.y * w10 + v11.y * w11;
    acc[2] += v00.z * w00 + v01.z * w01 + v10.z * w10 + v11.z * w11;
}

// ---------------------------------------------------------------------------
// Kernel 4: grid gen + mipmap warp. Thread = 2 adjacent px in w; warp tile
// 16w x 4h (same gather footprint area as before, half the store
// instructions, vectorized 16B/8B stores).
// ---------------------------------------------------------------------------
__global__ void warp_kernel(float* __restrict__ out,
                            float* __restrict__ grid_out) {
    int n  = blockIdx.z;
    int w0 = (blockIdx.x * 8 + threadIdx.x) * 2;
    int h  = blockIdx.y * 16 + threadIdx.y;

    BParam bp = g_bp[n];

    float wc  = ((float)w0 + 0.5f) * (2.f / (float)WW) - 1.f;
    float hc  = ((float)h + 0.5f) * (2.f / (float)HH) - 1.f;
    float dgx = bp.m00 * (2.f / (float)WW);          // per +1 in w
    float dgy = bp.m10 * (2.f / (float)WW);
    float gx0 = bp.m00 * wc + bp.m01 * hc + bp.m02;
    float gy0 = bp.m10 * wc + bp.m11 * hc + bp.m12;
    float gx1 = gx0 + dgx;
    float gy1 = gy0 + dgy;

    {   // grid store: 2 px = float4, 16B aligned (w0 even), evict-first
        float* gp = grid_out + ((size_t)n * 65536 + (size_t)h * 256 + w0) * 2;
        __stcs(reinterpret_cast<float4*>(gp), make_float4(gx0, gy0, gx1, gy1));
    }

    int l0 = bp.l0;
    float w1 = bp.w1;
    float wgt0 = 1.f - w1;

    const uint2* b0; int s0;
    if (l0 == 0)      { b0 = g_img4  + (size_t)n * 65536; s0 = 256; }
    else if (l0 == 1) { b0 = g_pyr14 + (size_t)n * 16384; s0 = 128; }
    else              { b0 = g_pyr24 + (size_t)n * 4096;  s0 = 64;  }

    const uint2* b1 = nullptr; int s1 = 0;
    if (w1 > 0.f) {
        if (l0 == 0)      { b1 = g_pyr14 + (size_t)n * 16384; s1 = 128; }
        else if (l0 == 1) { b1 = g_pyr24 + (size_t)n * 4096;  s1 = 64;  }
        else              { b1 = g_pyr34 + (size_t)n * 1024;  s1 = 32;  }
    }

    float a0[3] = {0.f, 0.f, 0.f};
    float a1[3] = {0.f, 0.f, 0.f};
    sample4(b0, s0, gx0, gy0, wgt0, a0);
    sample4(b0, s0, gx1, gy1, wgt0, a1);
    if (b1) {
        sample4(b1, s1, gx0, gy0, w1, a0);
        sample4(b1, s1, gx1, gy1, w1, a1);
    }

    // out stores: 3 channels x float2 (2 px along w), 8B aligned.
    float* o = out + (size_t)n * 3 * 65536 + (size_t)h * 256 + w0;
    __stcs(reinterpret_cast<float2*>(o),          make_float2(a0[0], a1[0]));
    __stcs(reinterpret_cast<float2*>(o + 65536),  make_float2(a0[1], a1[1]));
    __stcs(reinterpret_cast<float2*>(o + 131072), make_float2(a0[2], a1[2]));
}

// ---------------------------------------------------------------------------
extern "C" void kernel_launch(void* const* d_in, const int* in_sizes, int n_in,
                              void* d_out, int out_size) {
    const float* img  = (const float*)d_in[0];
    const float* feat = (const float*)d_in[1];
    const float* lw   = (const float*)d_in[2];
    const float* lb   = (const float*)d_in[3];

    float* base   = (float*)d_out;
    float* out_p  = base;                                   // N*C*H*W
    float* grid_p = base + (size_t)NB * CCH * HH * WW;
    float* mat_p  = grid_p + (size_t)NB * HH * WW * 2;
    float* aff_p  = mat_p + NB * 6;

    params_kernel<<<NB, 128>>>(feat, lw, lb, mat_p, aff_p);
    hwc0_kernel<<<NB * 256, 256>>>(img);                    // transpose + down0
    {
        dim3 g(20, NB);                                     // 5120 threads/batch
        down12_kernel<<<g, 256>>>();
    }

    dim3 blk(8, 16);
    dim3 grd(WW / 16, HH / 16, NB);
    warp_kernel<<<grd, blk>>>(out_p, grid_p);
}